// round 2
// baseline (speedup 1.0000x reference)
#include <cuda_runtime.h>
#include <math.h>

#define EPSBN 1e-5f

#define NB 8
#define CIN 3
#define HIMG 256
#define WIMG 256
#define DD 64
#define KC 1024
#define HP 128
#define WP 128
#define NPTS (NB*HP*WP)            /* 131072 */
#define YELEMS (NB*CIN*HIMG*WIMG)  /* 1572864 */
#define BNCNT (NB*HIMG*WIMG)       /* 524288 per channel */

// ---------------- scratch (device globals; allocation-free) ----------------
__device__ float g_h[NB*DD*HIMG*WIMG];    // conv1 out (pre-BN), NCHW
__device__ float g_pool[NPTS*DD];         // pooled, NHWC flat [N,64]
__device__ float g_quant[NPTS*DD];        // gathered codes, NHWC flat
__device__ int   g_idx[NPTS];
__device__ float g_y2[YELEMS];            // conv2 out (pre-BN), NCHW
__device__ float g_e2[KC];                // ||e||^2
__device__ float g_cw[48*64];             // collapsed conv2 weights
__device__ float g_part1[64*32*2];
__device__ float g_part2[3*32*2];
__device__ float g_bn1[64*2];             // (scale, shift)
__device__ float g_bn2[3*2];
__device__ float g_losspart[1024];

// ============================================================
// conv1 + bias: x[8,3,256,256] -> g_h[8,64,256,256]
// ============================================================
__global__ void __launch_bounds__(256) conv1_k(const float* __restrict__ x,
                                               const float* __restrict__ w,
                                               const float* __restrict__ bias)
{
    __shared__ float s_in[3][34][34];
    __shared__ float s_w[64*27];
    __shared__ float s_b[64];
    int tx = threadIdx.x, ty = threadIdx.y;
    int tid = ty*32 + tx;
    int x0 = blockIdx.x*32, y0 = blockIdx.y*32, b = blockIdx.z;

    for (int i = tid; i < 64*27; i += 256) s_w[i] = w[i];
    if (tid < 64) s_b[tid] = bias[tid];
    for (int i = tid; i < 3*34*34; i += 256) {
        int c = i / (34*34); int r = i % (34*34);
        int yy = r / 34, xx = r % 34;
        int gy = y0 + yy - 1, gx = x0 + xx - 1;
        float v = 0.f;
        if (gy >= 0 && gy < 256 && gx >= 0 && gx < 256)
            v = x[((b*3 + c)*256 + gy)*256 + gx];
        s_in[c][yy][xx] = v;
    }
    __syncthreads();

    float rin[3][6][3];
#pragma unroll
    for (int c = 0; c < 3; c++)
#pragma unroll
        for (int r = 0; r < 6; r++)
#pragma unroll
            for (int q = 0; q < 3; q++)
                rin[c][r][q] = s_in[c][ty*4 + r][tx + q];

    int ox = x0 + tx, oy = y0 + ty*4;
    for (int co = 0; co < 64; co++) {
        float bb = s_b[co];
        float a0 = bb, a1 = bb, a2 = bb, a3 = bb;
#pragma unroll
        for (int c = 0; c < 3; c++)
#pragma unroll
            for (int ky = 0; ky < 3; ky++)
#pragma unroll
                for (int kx = 0; kx < 3; kx++) {
                    float wv = s_w[co*27 + c*9 + ky*3 + kx];
                    a0 = fmaf(rin[c][0+ky][kx], wv, a0);
                    a1 = fmaf(rin[c][1+ky][kx], wv, a1);
                    a2 = fmaf(rin[c][2+ky][kx], wv, a2);
                    a3 = fmaf(rin[c][3+ky][kx], wv, a3);
                }
        int base = ((b*64 + co)*256 + oy)*256 + ox;
        g_h[base]       = a0;
        g_h[base + 256] = a1;
        g_h[base + 512] = a2;
        g_h[base + 768] = a3;
    }
}

// ============================================================
// BN stats stage 1: per (channel, slice) partial sum/sumsq
// ============================================================
__global__ void __launch_bounds__(256) stats_k(const float* __restrict__ src, int C,
                                               float* __restrict__ part)
{
    int c = blockIdx.x, s = blockIdx.y, t = threadIdx.x;
    float sum = 0.f, sq = 0.f;
    int i0 = s * 16384;
    for (int i = i0 + t; i < i0 + 16384; i += 256) {
        int b = i >> 16, p = i & 65535;
        float v = src[(b*C + c)*65536 + p];
        sum += v; sq = fmaf(v, v, sq);
    }
    __shared__ float ss[256], s2[256];
    ss[t] = sum; s2[t] = sq; __syncthreads();
    for (int o = 128; o > 0; o >>= 1) {
        if (t < o) { ss[t] += ss[t+o]; s2[t] += s2[t+o]; }
        __syncthreads();
    }
    if (t == 0) { part[(c*32 + s)*2] = ss[0]; part[(c*32 + s)*2 + 1] = s2[0]; }
}

// stage 2: scale/shift per channel
__global__ void finalize_k(const float* __restrict__ part,
                           const float* __restrict__ gamma,
                           const float* __restrict__ beta,
                           float* __restrict__ out, int C)
{
    int c = threadIdx.x;
    if (c >= C) return;
    float sum = 0.f, sq = 0.f;
    for (int s = 0; s < 32; s++) { sum += part[(c*32+s)*2]; sq += part[(c*32+s)*2+1]; }
    float inv = 1.f / (float)BNCNT;
    float mean = sum * inv;
    float var = sq * inv - mean*mean;
    float scale = gamma[c] * rsqrtf(var + EPSBN);
    out[c*2] = scale;
    out[c*2+1] = beta[c] - mean*scale;
}

// ============================================================
// fused BN1 + ReLU + maxpool2 + NCHW->NHWC transpose -> g_pool
// one block = 32 pooled positions (one row segment) x 64 channels
// ============================================================
__global__ void __launch_bounds__(256) bnpool_k()
{
    __shared__ float s[32*65];
    __shared__ float s_ss[128];
    int t = threadIdx.x;
    if (t < 128) s_ss[t] = g_bn1[t];
    int n0 = blockIdx.x * 32;
    int b = n0 >> 14;
    int rem = n0 & 16383;
    int py = rem >> 7;
    int px0 = rem & 127;
    int xi = t & 31;
    int d0 = t >> 5;
    __syncthreads();
#pragma unroll
    for (int j = 0; j < 8; j++) {
        int d = d0 + j*8;
        int addr = ((b*64 + d)*256 + 2*py)*256 + 2*(px0 + xi);
        float v00 = g_h[addr],     v01 = g_h[addr+1];
        float v10 = g_h[addr+256], v11 = g_h[addr+257];
        float sc = s_ss[d*2], sh = s_ss[d*2+1];
        v00 = fmaxf(fmaf(v00, sc, sh), 0.f);
        v01 = fmaxf(fmaf(v01, sc, sh), 0.f);
        v10 = fmaxf(fmaf(v10, sc, sh), 0.f);
        v11 = fmaxf(fmaf(v11, sc, sh), 0.f);
        s[xi*65 + d] = fmaxf(fmaxf(v00, v01), fmaxf(v10, v11));
    }
    __syncthreads();
#pragma unroll
    for (int j = 0; j < 8; j++) {
        int e = j*256 + t;
        int r = e >> 6, c = e & 63;
        g_pool[(n0 + r)*64 + c] = s[r*65 + c];
    }
}

// ============================================================
// ||e||^2 per code (warp per code)
// ============================================================
__global__ void __launch_bounds__(256) e2_k(const float* __restrict__ embed)
{
    int t = threadIdx.x;
    int code = blockIdx.x*8 + (t >> 5);
    int lane = t & 31;
    float a = embed[code*64 + lane];
    float bb = embed[code*64 + 32 + lane];
    float s = a*a + bb*bb;
#pragma unroll
    for (int o = 16; o > 0; o >>= 1)
        s += __shfl_down_sync(0xffffffffu, s, o);
    if (lane == 0) g_e2[code] = s;
}

// ============================================================
// VQ: distance GEMM (128 rows x 1024 codes, k=64) + argmin +
// gather + commit-loss partial. XOR-swizzled smem, 48KB exactly.
// ============================================================
__global__ void __launch_bounds__(256) vq_k(const float* __restrict__ embed)
{
    __shared__ float s_f[128*64];
    __shared__ float s_e[64*64];
    int t = threadIdx.x;
    int tx = t & 15, ty = t >> 4;
    int row0 = blockIdx.x * 128;

    for (int e = t; e < 8192; e += 256) {
        int r = e >> 6, k = e & 63;
        s_f[r*64 + (k ^ (r & 31))] = g_pool[row0*64 + e];
    }

    float mn[8]; int mi[8];
#pragma unroll
    for (int i = 0; i < 8; i++) { mn[i] = INFINITY; mi[i] = 0; }

    for (int ch = 0; ch < 16; ch++) {
        __syncthreads();
        for (int e = t; e < 4096; e += 256) {
            int c = e >> 6, k = e & 63;
            s_e[c*64 + (k ^ (c & 31))] = embed[ch*4096 + e];
        }
        __syncthreads();

        float acc[8][4];
#pragma unroll
        for (int i = 0; i < 8; i++)
#pragma unroll
            for (int j = 0; j < 4; j++) acc[i][j] = 0.f;

#pragma unroll
        for (int k = 0; k < 64; k++) {
            float a[8], bv[4];
#pragma unroll
            for (int i = 0; i < 8; i++) {
                int r = ty + 16*i;
                a[i] = s_f[r*64 + (k ^ (r & 31))];
            }
#pragma unroll
            for (int j = 0; j < 4; j++) {
                int c = tx + 16*j;
                bv[j] = s_e[c*64 + (k ^ (c & 31))];
            }
#pragma unroll
            for (int i = 0; i < 8; i++)
#pragma unroll
                for (int j = 0; j < 4; j++)
                    acc[i][j] = fmaf(a[i], bv[j], acc[i][j]);
        }

#pragma unroll
        for (int j = 0; j < 4; j++) {
            int c = ch*64 + tx + 16*j;
            float e2v = g_e2[c];
#pragma unroll
            for (int i = 0; i < 8; i++) {
                float d = fmaf(-2.f, acc[i][j], e2v);
                if (d < mn[i]) { mn[i] = d; mi[i] = c; }
            }
        }
    }

    // reduce (min,idx) over the 16 lanes sharing each row group
#pragma unroll
    for (int i = 0; i < 8; i++) {
#pragma unroll
        for (int off = 8; off > 0; off >>= 1) {
            float vo = __shfl_down_sync(0xffffffffu, mn[i], off, 16);
            int   io = __shfl_down_sync(0xffffffffu, mi[i], off, 16);
            if (vo < mn[i] || (vo == mn[i] && io < mi[i])) { mn[i] = vo; mi[i] = io; }
        }
    }
    __syncthreads();
    int* s_rowidx = (int*)s_e;
    if (tx == 0) {
#pragma unroll
        for (int i = 0; i < 8; i++) s_rowidx[ty + 16*i] = mi[i];
    }
    __syncthreads();

    float lacc = 0.f;
    for (int e = t; e < 8192; e += 256) {
        int r = e >> 6, d = e & 63;
        int ci = s_rowidx[r];
        float qv = embed[ci*64 + d];
        float fv = s_f[r*64 + (d ^ (r & 31))];
        float df = qv - fv;
        lacc = fmaf(df, df, lacc);
        g_quant[row0*64 + e] = qv;
    }
    if (t < 128) g_idx[row0 + t] = s_rowidx[t];

    float* s_red = ((float*)s_e) + 256;
    s_red[t] = lacc;
    __syncthreads();
    for (int o = 128; o > 0; o >>= 1) {
        if (t < o) s_red[t] += s_red[t+o];
        __syncthreads();
    }
    if (t == 0) g_losspart[blockIdx.x] = s_red[0];
}

// ============================================================
// collapse conv2 3x3-over-upsample into 4 phase x 2x2 kernels
// ============================================================
__global__ void __launch_bounds__(256) collapse_k(const float* __restrict__ w2)
{
    int e = blockIdx.x*256 + threadIdx.x;   // 3072 entries
    if (e >= 48*64) return;
    int d = e & 63;
    int rest = e >> 6;          // 0..47
    int tap = rest & 3;
    int tx_ = tap & 1, ty_ = tap >> 1;
    int co = (rest >> 2) % 3;
    int ph = rest / 12;
    int px = ph & 1, py = ph >> 1;
    float s = 0.f;
    for (int ky = 0; ky < 3; ky++) {
        int mapy = (py == 0) ? ((ky == 0) ? 0 : 1) : ((ky < 2) ? 0 : 1);
        if (mapy != ty_) continue;
        for (int kx = 0; kx < 3; kx++) {
            int mapx = (px == 0) ? ((kx == 0) ? 0 : 1) : ((kx < 2) ? 0 : 1);
            if (mapx != tx_) continue;
            s += w2[((co*64 + d)*3 + ky)*3 + kx];
        }
    }
    g_cw[e] = s;
}

// ============================================================
// decoder: nearest-x2 upsample fused with conv2 (collapsed 2x2)
// block: q tile 16 rows x 32 cols, thread = 1x2 q pixels
// ============================================================
#define DCK 16
__global__ void __launch_bounds__(256) conv2up_k(const float* __restrict__ bias)
{
    __shared__ float s_q[DCK][18][34];
    __shared__ float s_cw[48][DCK];
    int t = threadIdx.x;
    int tx = t & 15, ty = t >> 4;
    int x0 = blockIdx.x*32, y0 = blockIdx.y*16, bb = blockIdx.z;

    float acc[2][2][2][3];   // [xi][py][px][co]
#pragma unroll
    for (int a1 = 0; a1 < 2; a1++)
#pragma unroll
        for (int a2 = 0; a2 < 2; a2++)
#pragma unroll
            for (int a3 = 0; a3 < 2; a3++)
#pragma unroll
                for (int a4 = 0; a4 < 3; a4++) acc[a1][a2][a3][a4] = 0.f;

    for (int ch = 0; ch < 64/DCK; ch++) {
        __syncthreads();
        for (int e = t; e < 48*DCK; e += 256) {
            int row = e >> 4, dl = e & (DCK-1);
            s_cw[row][dl] = g_cw[row*64 + ch*DCK + dl];
        }
        for (int e = t; e < 612*DCK; e += 256) {
            int dl = e & (DCK-1);
            int cell = e >> 4;
            int r = cell / 34, c = cell % 34;
            int qy = y0 - 1 + r, qx = x0 - 1 + c;
            float v = 0.f;
            if (qy >= 0 && qy < 128 && qx >= 0 && qx < 128)
                v = g_quant[((bb*128 + qy)*128 + qx)*64 + ch*DCK + dl];
            s_q[dl][r][c] = v;
        }
        __syncthreads();

#pragma unroll 4
        for (int dl = 0; dl < DCK; dl++) {
            float qv[3][4];
#pragma unroll
            for (int a = 0; a < 3; a++)
#pragma unroll
                for (int c = 0; c < 4; c++)
                    qv[a][c] = s_q[dl][ty + a][2*tx + c];
#pragma unroll
            for (int co = 0; co < 3; co++)
#pragma unroll
                for (int py = 0; py < 2; py++)
#pragma unroll
                    for (int px = 0; px < 2; px++) {
#pragma unroll
                        for (int ty_ = 0; ty_ < 2; ty_++)
#pragma unroll
                            for (int tx_ = 0; tx_ < 2; tx_++) {
                                float wv = s_cw[((py*2+px)*3+co)*4 + ty_*2+tx_][dl];
#pragma unroll
                                for (int xi = 0; xi < 2; xi++)
                                    acc[xi][py][px][co] =
                                        fmaf(qv[py+ty_][xi+px+tx_], wv, acc[xi][py][px][co]);
                            }
                    }
        }
    }

    int qy = y0 + ty;
#pragma unroll
    for (int co = 0; co < 3; co++) {
        float bv = bias[co];
#pragma unroll
        for (int xi = 0; xi < 2; xi++) {
            int qx = x0 + 2*tx + xi;
#pragma unroll
            for (int py = 0; py < 2; py++)
#pragma unroll
                for (int px = 0; px < 2; px++) {
                    int Y = 2*qy + py, X = 2*qx + px;
                    g_y2[((bb*3 + co) << 16) + (Y << 8) + X] = acc[xi][py][px][co] + bv;
                }
        }
    }
}

// ============================================================
// BN2 apply + tanh -> d_out[0 .. 1572863]
// ============================================================
__global__ void __launch_bounds__(256) bn2tanh_k(float* __restrict__ out)
{
    int e = blockIdx.x*256 + threadIdx.x;
    if (e >= YELEMS) return;
    int c = (e >> 16) % 3;
    float v = g_y2[e];
    out[e] = tanhf(fmaf(v, g_bn2[c*2], g_bn2[c*2+1]));
}

__global__ void __launch_bounds__(256) idx_k(float* __restrict__ out)
{
    int e = blockIdx.x*256 + threadIdx.x;
    if (e < NPTS) out[YELEMS + e] = (float)g_idx[e];
}

__global__ void __launch_bounds__(256) loss_k(float* __restrict__ out)
{
    __shared__ float s[256];
    int t = threadIdx.x;
    s[t] = g_losspart[t] + g_losspart[t+256] + g_losspart[t+512] + g_losspart[t+768];
    __syncthreads();
    for (int o = 128; o > 0; o >>= 1) {
        if (t < o) s[t] += s[t+o];
        __syncthreads();
    }
    if (t == 0) out[YELEMS + NPTS] = 0.25f * s[0] / (float)(NPTS * DD);
}

// ============================================================
extern "C" void kernel_launch(void* const* d_in, const int* in_sizes, int n_in,
                              void* d_out, int out_size)
{
    const float* x   = (const float*)d_in[0];
    const float* w1  = (const float*)d_in[1];
    const float* b1  = (const float*)d_in[2];
    const float* g1  = (const float*)d_in[3];
    const float* be1 = (const float*)d_in[4];
    const float* em  = (const float*)d_in[5];
    const float* w2  = (const float*)d_in[6];
    const float* b2  = (const float*)d_in[7];
    const float* g2  = (const float*)d_in[8];
    const float* be2 = (const float*)d_in[9];
    float* out = (float*)d_out;
    (void)in_sizes; (void)n_in; (void)out_size;

    float* p1; float* p2; float* bn1p; float* bn2p;
    cudaGetSymbolAddress((void**)&p1,   g_part1);
    cudaGetSymbolAddress((void**)&p2,   g_part2);
    cudaGetSymbolAddress((void**)&bn1p, g_bn1);
    cudaGetSymbolAddress((void**)&bn2p, g_bn2);
    float* hptr; float* y2ptr;
    cudaGetSymbolAddress((void**)&hptr,  g_h);
    cudaGetSymbolAddress((void**)&y2ptr, g_y2);

    e2_k<<<128, 256>>>(em);
    collapse_k<<<12, 256>>>(w2);
    conv1_k<<<dim3(8,8,8), dim3(32,8)>>>(x, w1, b1);
    stats_k<<<dim3(64,32), 256>>>(hptr, 64, p1);
    finalize_k<<<1, 64>>>(p1, g1, be1, bn1p, 64);
    bnpool_k<<<NPTS/32, 256>>>();
    vq_k<<<NPTS/128, 256>>>(em);
    conv2up_k<<<dim3(4,8,8), 256>>>(b2);
    stats_k<<<dim3(3,32), 256>>>(y2ptr, 3, p2);
    finalize_k<<<1, 32>>>(p2, g2, be2, bn2p, 3);
    bn2tanh_k<<<(YELEMS+255)/256, 256>>>(out);
    idx_k<<<NPTS/256, 256>>>(out);
    loss_k<<<1, 256>>>(out);
}

// round 4
// speedup vs baseline: 1.4919x; 1.4919x over previous
#include <cuda_runtime.h>
#include <cuda_bf16.h>
#include <cstdint>
#include <math.h>

#define EPSBN 1e-5f

#define NB 8
#define CIN 3
#define HIMG 256
#define WIMG 256
#define DD 64
#define KC 1024
#define HP 128
#define WP 128
#define NPTS (NB*HP*WP)            /* 131072 */
#define YELEMS (NB*CIN*HIMG*WIMG)  /* 1572864 */
#define BNCNT (NB*HIMG*WIMG)       /* 524288 per channel */

// ---------------- scratch (device globals; allocation-free) ----------------
__device__ float g_h[NB*DD*HIMG*WIMG];    // conv1 out (pre-BN), NCHW
__device__ float g_pool[NPTS*DD];         // pooled fp32, NHWC flat [N,64]
__device__ __align__(16) __nv_bfloat16 g_fhi[NPTS*DD];
__device__ __align__(16) __nv_bfloat16 g_flo[NPTS*DD];
__device__ __align__(16) __nv_bfloat16 g_ehi[KC*DD];
__device__ __align__(16) __nv_bfloat16 g_elo[KC*DD];
__device__ float g_quant[NPTS*DD];        // gathered codes, NHWC flat
__device__ int   g_idx[NPTS];
__device__ float g_y2[YELEMS];            // conv2 out (pre-BN), NCHW
__device__ float g_e2[KC];                // ||e||^2
__device__ float g_cw[48*64];             // collapsed conv2 weights
__device__ float g_part1[64*32*2];
__device__ float g_part2[3*32*2];
__device__ float g_bn1[64*2];             // (scale, shift)
__device__ float g_bn2[3*2];
__device__ float g_losspart[1024];

// ---------------- mma helpers ----------------
#define LDSM_X4(r0,r1,r2,r3,addr) \
    asm volatile("ldmatrix.sync.aligned.m8n8.x4.shared.b16 {%0,%1,%2,%3},[%4];" \
        : "=r"(r0),"=r"(r1),"=r"(r2),"=r"(r3) : "r"(addr))
#define LDSM_X2(r0,r1,addr) \
    asm volatile("ldmatrix.sync.aligned.m8n8.x2.shared.b16 {%0,%1},[%2];" \
        : "=r"(r0),"=r"(r1) : "r"(addr))
#define MMA16816(c,a0,a1,a2,a3,b0,b1) \
    asm volatile("mma.sync.aligned.m16n8k16.row.col.f32.bf16.bf16.f32 " \
        "{%0,%1,%2,%3},{%4,%5,%6,%7},{%8,%9},{%0,%1,%2,%3};" \
        : "+f"((c)[0]),"+f"((c)[1]),"+f"((c)[2]),"+f"((c)[3]) \
        : "r"(a0),"r"(a1),"r"(a2),"r"(a3),"r"(b0),"r"(b1))

__device__ __forceinline__ bool better(float da, int ia, float db, int ib) {
    return da < db || (da == db && ia < ib);
}
__device__ __forceinline__ void ins2(float d, int i, float& d1, int& i1,
                                     float& d2, int& i2) {
    if (better(d, i, d1, i1)) { d2 = d1; i2 = i1; d1 = d; i1 = i; }
    else if (better(d, i, d2, i2)) { d2 = d; i2 = i; }
}

// ============================================================
// conv1 + bias: x[8,3,256,256] -> g_h[8,64,256,256]
// ============================================================
__global__ void __launch_bounds__(256) conv1_k(const float* __restrict__ x,
                                               const float* __restrict__ w,
                                               const float* __restrict__ bias)
{
    __shared__ float s_in[3][34][34];
    __shared__ float s_w[64*27];
    __shared__ float s_b[64];
    int tx = threadIdx.x, ty = threadIdx.y;
    int tid = ty*32 + tx;
    int x0 = blockIdx.x*32, y0 = blockIdx.y*32, b = blockIdx.z;

    for (int i = tid; i < 64*27; i += 256) s_w[i] = w[i];
    if (tid < 64) s_b[tid] = bias[tid];
    for (int i = tid; i < 3*34*34; i += 256) {
        int c = i / (34*34); int r = i % (34*34);
        int yy = r / 34, xx = r % 34;
        int gy = y0 + yy - 1, gx = x0 + xx - 1;
        float v = 0.f;
        if (gy >= 0 && gy < 256 && gx >= 0 && gx < 256)
            v = x[((b*3 + c)*256 + gy)*256 + gx];
        s_in[c][yy][xx] = v;
    }
    __syncthreads();

    float rin[3][6][3];
#pragma unroll
    for (int c = 0; c < 3; c++)
#pragma unroll
        for (int r = 0; r < 6; r++)
#pragma unroll
            for (int q = 0; q < 3; q++)
                rin[c][r][q] = s_in[c][ty*4 + r][tx + q];

    int ox = x0 + tx, oy = y0 + ty*4;
    for (int co = 0; co < 64; co++) {
        float bb = s_b[co];
        float a0 = bb, a1 = bb, a2 = bb, a3 = bb;
#pragma unroll
        for (int c = 0; c < 3; c++)
#pragma unroll
            for (int ky = 0; ky < 3; ky++)
#pragma unroll
                for (int kx = 0; kx < 3; kx++) {
                    float wv = s_w[co*27 + c*9 + ky*3 + kx];
                    a0 = fmaf(rin[c][0+ky][kx], wv, a0);
                    a1 = fmaf(rin[c][1+ky][kx], wv, a1);
                    a2 = fmaf(rin[c][2+ky][kx], wv, a2);
                    a3 = fmaf(rin[c][3+ky][kx], wv, a3);
                }
        int base = ((b*64 + co)*256 + oy)*256 + ox;
        g_h[base]       = a0;
        g_h[base + 256] = a1;
        g_h[base + 512] = a2;
        g_h[base + 768] = a3;
    }
}

// ============================================================
// BN stats stage 1
// ============================================================
__global__ void __launch_bounds__(256) stats_k(const float* __restrict__ src, int C,
                                               float* __restrict__ part)
{
    int c = blockIdx.x, s = blockIdx.y, t = threadIdx.x;
    float sum = 0.f, sq = 0.f;
    int i0 = s * 16384;
    for (int i = i0 + t; i < i0 + 16384; i += 256) {
        int b = i >> 16, p = i & 65535;
        float v = src[(b*C + c)*65536 + p];
        sum += v; sq = fmaf(v, v, sq);
    }
    __shared__ float ss[256], s2[256];
    ss[t] = sum; s2[t] = sq; __syncthreads();
    for (int o = 128; o > 0; o >>= 1) {
        if (t < o) { ss[t] += ss[t+o]; s2[t] += s2[t+o]; }
        __syncthreads();
    }
    if (t == 0) { part[(c*32 + s)*2] = ss[0]; part[(c*32 + s)*2 + 1] = s2[0]; }
}

__global__ void finalize_k(const float* __restrict__ part,
                           const float* __restrict__ gamma,
                           const float* __restrict__ beta,
                           float* __restrict__ out, int C)
{
    int c = threadIdx.x;
    if (c >= C) return;
    float sum = 0.f, sq = 0.f;
    for (int s = 0; s < 32; s++) { sum += part[(c*32+s)*2]; sq += part[(c*32+s)*2+1]; }
    float inv = 1.f / (float)BNCNT;
    float mean = sum * inv;
    float var = sq * inv - mean*mean;
    float scale = gamma[c] * rsqrtf(var + EPSBN);
    out[c*2] = scale;
    out[c*2+1] = beta[c] - mean*scale;
}

// ============================================================
// fused BN1 + ReLU + maxpool2 + transpose -> g_pool (+ bf16 hi/lo)
// ============================================================
__global__ void __launch_bounds__(256) bnpool_k()
{
    __shared__ float s[32*65];
    __shared__ float s_ss[128];
    int t = threadIdx.x;
    if (t < 128) s_ss[t] = g_bn1[t];
    int n0 = blockIdx.x * 32;
    int b = n0 >> 14;
    int rem = n0 & 16383;
    int py = rem >> 7;
    int px0 = rem & 127;
    int xi = t & 31;
    int d0 = t >> 5;
    __syncthreads();
#pragma unroll
    for (int j = 0; j < 8; j++) {
        int d = d0 + j*8;
        int addr = ((b*64 + d)*256 + 2*py)*256 + 2*(px0 + xi);
        float v00 = g_h[addr],     v01 = g_h[addr+1];
        float v10 = g_h[addr+256], v11 = g_h[addr+257];
        float sc = s_ss[d*2], sh = s_ss[d*2+1];
        v00 = fmaxf(fmaf(v00, sc, sh), 0.f);
        v01 = fmaxf(fmaf(v01, sc, sh), 0.f);
        v10 = fmaxf(fmaf(v10, sc, sh), 0.f);
        v11 = fmaxf(fmaf(v11, sc, sh), 0.f);
        s[xi*65 + d] = fmaxf(fmaxf(v00, v01), fmaxf(v10, v11));
    }
    __syncthreads();
#pragma unroll
    for (int j = 0; j < 8; j++) {
        int e = j*256 + t;
        int r = e >> 6, c = e & 63;
        float v = s[r*65 + c];
        int gi = (n0 + r)*64 + c;
        g_pool[gi] = v;
        __nv_bfloat16 h = __float2bfloat16(v);
        g_fhi[gi] = h;
        g_flo[gi] = __float2bfloat16(v - __bfloat162float(h));
    }
}

// ============================================================
// embed prep: ||e||^2 + bf16 hi/lo split
// ============================================================
__global__ void __launch_bounds__(256) epre_k(const float* __restrict__ embed)
{
    int t = threadIdx.x;
    int code = blockIdx.x*8 + (t >> 5);
    int lane = t & 31;
    float a = embed[code*64 + lane];
    float bb = embed[code*64 + 32 + lane];
    __nv_bfloat16 ah = __float2bfloat16(a);
    __nv_bfloat16 bh = __float2bfloat16(bb);
    g_ehi[code*64 + lane] = ah;
    g_ehi[code*64 + 32 + lane] = bh;
    g_elo[code*64 + lane] = __float2bfloat16(a - __bfloat162float(ah));
    g_elo[code*64 + 32 + lane] = __float2bfloat16(bb - __bfloat162float(bh));
    float s = a*a + bb*bb;
#pragma unroll
    for (int o = 16; o > 0; o >>= 1)
        s += __shfl_down_sync(0xffffffffu, s, o);
    if (lane == 0) g_e2[code] = s;
}

// ============================================================
// VQ via tensor cores: D = f . e^T as bf16 hi/lo 3-GEMM split,
// fused approx top-2 argmin + exact fp32 refine + gather + loss.
// ============================================================
__global__ void __launch_bounds__(256,2) vq_k(const float* __restrict__ embed)
{
    __shared__ __align__(16) __nv_bfloat16 s_ahi[128*64];
    __shared__ __align__(16) __nv_bfloat16 s_alo[128*64];
    __shared__ __align__(16) __nv_bfloat16 s_ehi[64*64];
    __shared__ __align__(16) __nv_bfloat16 s_elo[64*64];
    int t = threadIdx.x;
    int warp = t >> 5, lane = t & 31;
    int row0 = blockIdx.x * 128;

    // ---- fill A smem (swizzled 16B chunks) ----
    {
        const uint4* sh = (const uint4*)(g_fhi + row0*64);
        const uint4* sl = (const uint4*)(g_flo + row0*64);
        uint4* dh = (uint4*)s_ahi;
        uint4* dl = (uint4*)s_alo;
#pragma unroll
        for (int j = 0; j < 4; j++) {
            int e = t + j*256;            // 1024 chunks
            int r = e >> 3, kc = e & 7;
            int dst = r*8 + (kc ^ (r & 7));
            dh[dst] = sh[e];
            dl[dst] = sl[e];
        }
    }
    // prefetch embed chunk 0
    const uint4* eh4 = (const uint4*)g_ehi;
    const uint4* el4 = (const uint4*)g_elo;
    uint4 bufh[2], bufl[2];
#pragma unroll
    for (int j = 0; j < 2; j++) {
        bufh[j] = eh4[t + j*256];
        bufl[j] = el4[t + j*256];
    }
    __syncthreads();

    // ---- hoist A fragments: rows warp*16..+15, all k, hi+lo ----
    unsigned int afrag[2][4][4];
    {
        unsigned int aHiB = (unsigned int)__cvta_generic_to_shared(s_ahi);
        unsigned int aLoB = (unsigned int)__cvta_generic_to_shared(s_alo);
        int ar = warp*16 + (lane & 15);
        int ahalf = lane >> 4;
#pragma unroll
        for (int ks = 0; ks < 4; ks++) {
            unsigned int off = (unsigned int)(ar*128 + (((ks*2 + ahalf) ^ (ar & 7)) << 4));
            LDSM_X4(afrag[0][ks][0], afrag[0][ks][1], afrag[0][ks][2], afrag[0][ks][3], aHiB + off);
            LDSM_X4(afrag[1][ks][0], afrag[1][ks][1], afrag[1][ks][2], afrag[1][ks][3], aLoB + off);
        }
    }

    float d1v[2] = {INFINITY, INFINITY}, d2v[2] = {INFINITY, INFINITY};
    int   i1v[2] = {0, 0},               i2v[2] = {0, 0};
    unsigned int eHiB = (unsigned int)__cvta_generic_to_shared(s_ehi);
    unsigned int eLoB = (unsigned int)__cvta_generic_to_shared(s_elo);
    int nb = lane & 7;
    int halfB = (lane >> 3) & 1;

    for (int ch = 0; ch < 16; ch++) {
        __syncthreads();
        {   // store prefetched chunk into swizzled smem
            uint4* dh = (uint4*)s_ehi;
            uint4* dl = (uint4*)s_elo;
#pragma unroll
            for (int j = 0; j < 2; j++) {
                int e = t + j*256;            // 512 chunks
                int r = e >> 3, kc = e & 7;
                int dst = r*8 + (kc ^ (r & 7));
                dh[dst] = bufh[j];
                dl[dst] = bufl[j];
            }
        }
        __syncthreads();
        if (ch + 1 < 16) {
#pragma unroll
            for (int j = 0; j < 2; j++) {
                bufh[j] = eh4[(ch+1)*512 + t + j*256];
                bufl[j] = el4[(ch+1)*512 + t + j*256];
            }
        }

        float acc[8][4];
#pragma unroll
        for (int f = 0; f < 8; f++)
#pragma unroll
            for (int q = 0; q < 4; q++) acc[f][q] = 0.f;

#pragma unroll
        for (int ks = 0; ks < 4; ks++) {
            unsigned int pc = (unsigned int)(((ks*2 + halfB) ^ nb) << 4) + (unsigned int)(nb*128);
#pragma unroll
            for (int f = 0; f < 8; f++) {
                unsigned int off = pc + (unsigned int)(f*1024);
                unsigned int bh0, bh1, bl0, bl1;
                LDSM_X2(bh0, bh1, eHiB + off);
                LDSM_X2(bl0, bl1, eLoB + off);
                MMA16816(acc[f], afrag[0][ks][0], afrag[0][ks][1], afrag[0][ks][2], afrag[0][ks][3], bh0, bh1);
                MMA16816(acc[f], afrag[0][ks][0], afrag[0][ks][1], afrag[0][ks][2], afrag[0][ks][3], bl0, bl1);
                MMA16816(acc[f], afrag[1][ks][0], afrag[1][ks][1], afrag[1][ks][2], afrag[1][ks][3], bh0, bh1);
            }
        }

        // chunk epilogue: dist = e2 - 2*dot, top-2 track
        int cb = ch*64 + (lane & 3)*2;
#pragma unroll
        for (int f = 0; f < 8; f++) {
            int c0 = cb + f*8, c1 = c0 + 1;
            float e20 = g_e2[c0], e21 = g_e2[c1];
            ins2(fmaf(-2.f, acc[f][0], e20), c0, d1v[0], i1v[0], d2v[0], i2v[0]);
            ins2(fmaf(-2.f, acc[f][1], e21), c1, d1v[0], i1v[0], d2v[0], i2v[0]);
            ins2(fmaf(-2.f, acc[f][2], e20), c0, d1v[1], i1v[1], d2v[1], i2v[1]);
            ins2(fmaf(-2.f, acc[f][3], e21), c1, d1v[1], i1v[1], d2v[1], i2v[1]);
        }
    }

    // ---- merge top-2 across the 4 lanes owning each row ----
    const unsigned FULL = 0xffffffffu;
#pragma unroll
    for (int off = 2; off > 0; off >>= 1) {
#pragma unroll
        for (int s = 0; s < 2; s++) {
            float od1 = __shfl_down_sync(FULL, d1v[s], off, 4);
            int   oi1 = __shfl_down_sync(FULL, i1v[s], off, 4);
            float od2 = __shfl_down_sync(FULL, d2v[s], off, 4);
            int   oi2 = __shfl_down_sync(FULL, i2v[s], off, 4);
            if (better(od1, oi1, d1v[s], i1v[s])) {
                if (better(d1v[s], i1v[s], od2, oi2)) { d2v[s] = d1v[s]; i2v[s] = i1v[s]; }
                else                                  { d2v[s] = od2;    i2v[s] = oi2; }
                d1v[s] = od1; i1v[s] = oi1;
            } else if (better(od1, oi1, d2v[s], i2v[s])) {
                d2v[s] = od1; i2v[s] = oi1;
            }
        }
    }
    __syncthreads();
    int* s_b1 = (int*)s_ehi;
    int* s_b2 = s_b1 + 128;
    if ((lane & 3) == 0) {
        int r = warp*16 + (lane >> 2);
        s_b1[r]     = i1v[0];  s_b2[r]     = i2v[0];
        s_b1[r + 8] = i1v[1];  s_b2[r + 8] = i2v[1];
    }
    __syncthreads();

    // ---- exact fp32 refine between top-2 candidates ----
    if (t < 128) {
        int ia = s_b1[t], ib = s_b2[t];
        if (ib != ia) {
            const float* frow = g_pool + (size_t)(row0 + t)*64;
            const float* ea = embed + (size_t)ia*64;
            const float* eb = embed + (size_t)ib*64;
            float da = 0.f, db = 0.f;
            for (int k = 0; k < 64; k++) {
                float fv = frow[k];
                da = fmaf(fv, ea[k], da);
                db = fmaf(fv, eb[k], db);
            }
            float dda = fmaf(-2.f, da, g_e2[ia]);
            float ddb = fmaf(-2.f, db, g_e2[ib]);
            if (better(ddb, ib, dda, ia)) s_b1[t] = ib;
        }
    }
    __syncthreads();

    // ---- gather quant + commit-loss partial ----
    float lacc = 0.f;
    for (int e = t; e < 8192; e += 256) {
        int r = e >> 6, d = e & 63;
        int ci = s_b1[r];
        float qv = embed[ci*64 + d];
        float fv = g_pool[(row0 + r)*64 + d];
        float df = qv - fv;
        lacc = fmaf(df, df, lacc);
        g_quant[row0*64 + e] = qv;
    }
    if (t < 128) g_idx[row0 + t] = s_b1[t];

    float* s_red = (float*)s_elo;
    s_red[t] = lacc;
    __syncthreads();
    for (int o = 128; o > 0; o >>= 1) {
        if (t < o) s_red[t] += s_red[t+o];
        __syncthreads();
    }
    if (t == 0) g_losspart[blockIdx.x] = s_red[0];
}

// ============================================================
// collapse conv2 3x3-over-upsample into 4 phase x 2x2 kernels
// ============================================================
__global__ void __launch_bounds__(256) collapse_k(const float* __restrict__ w2)
{
    int e = blockIdx.x*256 + threadIdx.x;
    if (e >= 48*64) return;
    int d = e & 63;
    int rest = e >> 6;
    int tap = rest & 3;
    int tx_ = tap & 1, ty_ = tap >> 1;
    int co = (rest >> 2) % 3;
    int ph = rest / 12;
    int px = ph & 1, py = ph >> 1;
    float s = 0.f;
    for (int ky = 0; ky < 3; ky++) {
        int mapy = (py == 0) ? ((ky == 0) ? 0 : 1) : ((ky < 2) ? 0 : 1);
        if (mapy != ty_) continue;
        for (int kx = 0; kx < 3; kx++) {
            int mapx = (px == 0) ? ((kx == 0) ? 0 : 1) : ((kx < 2) ? 0 : 1);
            if (mapx != tx_) continue;
            s += w2[((co*64 + d)*3 + ky)*3 + kx];
        }
    }
    g_cw[e] = s;
}

// ============================================================
// decoder: nearest-x2 upsample fused with conv2 (collapsed 2x2)
// ============================================================
#define DCK 16
__global__ void __launch_bounds__(256) conv2up_k(const float* __restrict__ bias)
{
    __shared__ float s_q[DCK][18][34];
    __shared__ float s_cw[48][DCK];
    int t = threadIdx.x;
    int tx = t & 15, ty = t >> 4;
    int x0 = blockIdx.x*32, y0 = blockIdx.y*16, bb = blockIdx.z;

    float acc[2][2][2][3];
#pragma unroll
    for (int a1 = 0; a1 < 2; a1++)
#pragma unroll
        for (int a2 = 0; a2 < 2; a2++)
#pragma unroll
            for (int a3 = 0; a3 < 2; a3++)
#pragma unroll
                for (int a4 = 0; a4 < 3; a4++) acc[a1][a2][a3][a4] = 0.f;

    for (int ch = 0; ch < 64/DCK; ch++) {
        __syncthreads();
        for (int e = t; e < 48*DCK; e += 256) {
            int row = e >> 4, dl = e & (DCK-1);
            s_cw[row][dl] = g_cw[row*64 + ch*DCK + dl];
        }
        for (int e = t; e < 612*DCK; e += 256) {
            int dl = e & (DCK-1);
            int cell = e >> 4;
            int r = cell / 34, c = cell % 34;
            int qy = y0 - 1 + r, qx = x0 - 1 + c;
            float v = 0.f;
            if (qy >= 0 && qy < 128 && qx >= 0 && qx < 128)
                v = g_quant[((bb*128 + qy)*128 + qx)*64 + ch*DCK + dl];
            s_q[dl][r][c] = v;
        }
        __syncthreads();

#pragma unroll 4
        for (int dl = 0; dl < DCK; dl++) {
            float qv[3][4];
#pragma unroll
            for (int a = 0; a < 3; a++)
#pragma unroll
                for (int c = 0; c < 4; c++)
                    qv[a][c] = s_q[dl][ty + a][2*tx + c];
#pragma unroll
            for (int co = 0; co < 3; co++)
#pragma unroll
                for (int py = 0; py < 2; py++)
#pragma unroll
                    for (int px = 0; px < 2; px++) {
#pragma unroll
                        for (int ty_ = 0; ty_ < 2; ty_++)
#pragma unroll
                            for (int tx_ = 0; tx_ < 2; tx_++) {
                                float wv = s_cw[((py*2+px)*3+co)*4 + ty_*2+tx_][dl];
#pragma unroll
                                for (int xi = 0; xi < 2; xi++)
                                    acc[xi][py][px][co] =
                                        fmaf(qv[py+ty_][xi+px+tx_], wv, acc[xi][py][px][co]);
                            }
                    }
        }
    }

    int qy = y0 + ty;
#pragma unroll
    for (int co = 0; co < 3; co++) {
        float bv = bias[co];
#pragma unroll
        for (int xi = 0; xi < 2; xi++) {
            int qx = x0 + 2*tx + xi;
#pragma unroll
            for (int py = 0; py < 2; py++)
#pragma unroll
                for (int px = 0; px < 2; px++) {
                    int Y = 2*qy + py, X = 2*qx + px;
                    g_y2[((bb*3 + co) << 16) + (Y << 8) + X] = acc[xi][py][px][co] + bv;
                }
        }
    }
}

// ============================================================
// BN2 apply + tanh -> d_out[0 .. 1572863]
// ============================================================
__global__ void __launch_bounds__(256) bn2tanh_k(float* __restrict__ out)
{
    int e = blockIdx.x*256 + threadIdx.x;
    if (e >= YELEMS) return;
    int c = (e >> 16) % 3;
    float v = g_y2[e];
    out[e] = tanhf(fmaf(v, g_bn2[c*2], g_bn2[c*2+1]));
}

__global__ void __launch_bounds__(256) idx_k(float* __restrict__ out)
{
    int e = blockIdx.x*256 + threadIdx.x;
    if (e < NPTS) out[YELEMS + e] = (float)g_idx[e];
}

__global__ void __launch_bounds__(256) loss_k(float* __restrict__ out)
{
    __shared__ float s[256];
    int t = threadIdx.x;
    s[t] = g_losspart[t] + g_losspart[t+256] + g_losspart[t+512] + g_losspart[t+768];
    __syncthreads();
    for (int o = 128; o > 0; o >>= 1) {
        if (t < o) s[t] += s[t+o];
        __syncthreads();
    }
    if (t == 0) out[YELEMS + NPTS] = 0.25f * s[0] / (float)(NPTS * DD);
}

// ============================================================
extern "C" void kernel_launch(void* const* d_in, const int* in_sizes, int n_in,
                              void* d_out, int out_size)
{
    const float* x   = (const float*)d_in[0];
    const float* w1  = (const float*)d_in[1];
    const float* b1  = (const float*)d_in[2];
    const float* g1  = (const float*)d_in[3];
    const float* be1 = (const float*)d_in[4];
    const float* em  = (const float*)d_in[5];
    const float* w2  = (const float*)d_in[6];
    const float* b2  = (const float*)d_in[7];
    const float* g2  = (const float*)d_in[8];
    const float* be2 = (const float*)d_in[9];
    float* out = (float*)d_out;
    (void)in_sizes; (void)n_in; (void)out_size;

    float* p1; float* p2; float* bn1p; float* bn2p;
    cudaGetSymbolAddress((void**)&p1,   g_part1);
    cudaGetSymbolAddress((void**)&p2,   g_part2);
    cudaGetSymbolAddress((void**)&bn1p, g_bn1);
    cudaGetSymbolAddress((void**)&bn2p, g_bn2);
    float* hptr; float* y2ptr;
    cudaGetSymbolAddress((void**)&hptr,  g_h);
    cudaGetSymbolAddress((void**)&y2ptr, g_y2);

    epre_k<<<128, 256>>>(em);
    collapse_k<<<12, 256>>>(w2);
    conv1_k<<<dim3(8,8,8), dim3(32,8)>>>(x, w1, b1);
    stats_k<<<dim3(64,32), 256>>>(hptr, 64, p1);
    finalize_k<<<1, 64>>>(p1, g1, be1, bn1p, 64);
    bnpool_k<<<NPTS/32, 256>>>();
    vq_k<<<NPTS/128, 256>>>(em);
    conv2up_k<<<dim3(4,8,8), 256>>>(b2);
    stats_k<<<dim3(3,32), 256>>>(y2ptr, 3, p2);
    finalize_k<<<1, 32>>>(p2, g2, be2, bn2p, 3);
    bn2tanh_k<<<(YELEMS+255)/256, 256>>>(out);
    idx_k<<<NPTS/256, 256>>>(out);
    loss_k<<<1, 256>>>(out);
}

// round 5
// speedup vs baseline: 1.6962x; 1.1369x over previous
#include <cuda_runtime.h>
#include <cuda_bf16.h>
#include <cstdint>
#include <math.h>

#define EPSBN 1e-5f

#define NB 8
#define CIN 3
#define HIMG 256
#define WIMG 256
#define DD 64
#define KC 1024
#define HP 128
#define WP 128
#define NPTS (NB*HP*WP)            /* 131072 */
#define YELEMS (NB*CIN*HIMG*WIMG)  /* 1572864 */
#define BNCNT (NB*HIMG*WIMG)       /* 524288 per channel */

// ---------------- scratch (device globals; allocation-free) ----------------
__device__ float g_praw[NPTS*DD];         // pooled RAW conv1 (pre-BN), NHWC flat
__device__ float g_pool[NPTS*DD];         // pooled post-BN fp32, NHWC flat
__device__ __align__(16) __nv_bfloat16 g_fhi[NPTS*DD];
__device__ __align__(16) __nv_bfloat16 g_flo[NPTS*DD];
__device__ __align__(16) __nv_bfloat16 g_ehi[KC*DD];
__device__ __align__(16) __nv_bfloat16 g_elo[KC*DD];
__device__ float g_quant[NPTS*DD];        // gathered codes, NHWC flat
__device__ float g_y2[YELEMS];            // conv2 out (pre-BN), NCHW
__device__ float g_e2[KC];                // ||e||^2
__device__ float g_cw[48*64];             // collapsed conv2 weights
__device__ float g_part1[64*512*2];       // per (channel, conv1-block) partials
__device__ float g_part2[3*32*2];
__device__ float g_bn1[64*2];             // (scale, shift)
__device__ float g_bn2[3*2];
__device__ float g_losspart[1024];

// ---------------- mma helpers ----------------
#define LDSM_X4(r0,r1,r2,r3,addr) \
    asm volatile("ldmatrix.sync.aligned.m8n8.x4.shared.b16 {%0,%1,%2,%3},[%4];" \
        : "=r"(r0),"=r"(r1),"=r"(r2),"=r"(r3) : "r"(addr))
#define LDSM_X2(r0,r1,addr) \
    asm volatile("ldmatrix.sync.aligned.m8n8.x2.shared.b16 {%0,%1},[%2];" \
        : "=r"(r0),"=r"(r1) : "r"(addr))
#define MMA16816(c,a0,a1,a2,a3,b0,b1) \
    asm volatile("mma.sync.aligned.m16n8k16.row.col.f32.bf16.bf16.f32 " \
        "{%0,%1,%2,%3},{%4,%5,%6,%7},{%8,%9},{%0,%1,%2,%3};" \
        : "+f"((c)[0]),"+f"((c)[1]),"+f"((c)[2]),"+f"((c)[3]) \
        : "r"(a0),"r"(a1),"r"(a2),"r"(a3),"r"(b0),"r"(b1))

__device__ __forceinline__ bool better(float da, int ia, float db, int ib) {
    return da < db || (da == db && ia < ib);
}
__device__ __forceinline__ void ins2(float d, int i, float& d1, int& i1,
                                     float& d2, int& i2) {
    if (better(d, i, d1, i1)) { d2 = d1; i2 = i1; d1 = d; i1 = i; }
    else if (better(d, i, d2, i2)) { d2 = d; i2 = i; }
}

// ============================================================
// conv1 + bias + fused BN1 stats + fused maxpool2 ->
//   g_praw (pooled raw, NHWC flat) + g_part1 (per-block stats)
// Valid because gamma=1 => scale>0 => pool commutes with affine+relu.
// ============================================================
__global__ void __launch_bounds__(256,2) conv1pool_k(const float* __restrict__ x,
                                                     const float* __restrict__ w,
                                                     const float* __restrict__ bias)
{
    __shared__ float s_in[3][34][34];
    __shared__ float s_w[64*27];
    __shared__ float s_b[64];
    __shared__ float s_sum[64*8];
    __shared__ float s_sq[64*8];
    extern __shared__ float s_pool[];   // [16][16][65]

    int tx = threadIdx.x, ty = threadIdx.y;
    int tid = ty*32 + tx;
    int wid = tid >> 5;
    int lane = tid & 31;
    int x0 = blockIdx.x*32, y0 = blockIdx.y*32, b = blockIdx.z;
    int bid = (b*8 + blockIdx.y)*8 + blockIdx.x;

    for (int i = tid; i < 64*27; i += 256) s_w[i] = w[i];
    if (tid < 64) s_b[tid] = bias[tid];
    for (int i = tid; i < 3*34*34; i += 256) {
        int c = i / (34*34); int r = i % (34*34);
        int yy = r / 34, xx = r % 34;
        int gy = y0 + yy - 1, gx = x0 + xx - 1;
        float v = 0.f;
        if (gy >= 0 && gy < 256 && gx >= 0 && gx < 256)
            v = x[((b*3 + c)*256 + gy)*256 + gx];
        s_in[c][yy][xx] = v;
    }
    __syncthreads();

    float rin[3][6][3];
#pragma unroll
    for (int c = 0; c < 3; c++)
#pragma unroll
        for (int r = 0; r < 6; r++)
#pragma unroll
            for (int q = 0; q < 3; q++)
                rin[c][r][q] = s_in[c][ty*4 + r][tx + q];

    const unsigned FULL = 0xffffffffu;
    int pxl = tx >> 1;
    int pr0 = ty*2;

    for (int co = 0; co < 64; co++) {
        float bb = s_b[co];
        float a0 = bb, a1 = bb, a2 = bb, a3 = bb;
#pragma unroll
        for (int c = 0; c < 3; c++)
#pragma unroll
            for (int ky = 0; ky < 3; ky++)
#pragma unroll
                for (int kx = 0; kx < 3; kx++) {
                    float wv = s_w[co*27 + c*9 + ky*3 + kx];
                    a0 = fmaf(rin[c][0+ky][kx], wv, a0);
                    a1 = fmaf(rin[c][1+ky][kx], wv, a1);
                    a2 = fmaf(rin[c][2+ky][kx], wv, a2);
                    a3 = fmaf(rin[c][3+ky][kx], wv, a3);
                }
        // stats over raw outputs
        float s = a0 + a1 + a2 + a3;
        float q = a0*a0; q = fmaf(a1,a1,q); q = fmaf(a2,a2,q); q = fmaf(a3,a3,q);
#pragma unroll
        for (int o = 16; o > 0; o >>= 1) {
            s += __shfl_xor_sync(FULL, s, o);
            q += __shfl_xor_sync(FULL, q, o);
        }
        if (lane == 0) { s_sum[co*8 + wid] = s; s_sq[co*8 + wid] = q; }
        // maxpool 2x2: vertical pairs in-thread, horizontal via shfl
        float m0 = fmaxf(a0, a1);
        float m1 = fmaxf(a2, a3);
        m0 = fmaxf(m0, __shfl_xor_sync(FULL, m0, 1));
        m1 = fmaxf(m1, __shfl_xor_sync(FULL, m1, 1));
        if ((tx & 1) == 0) {
            s_pool[(pr0*16 + pxl)*65 + co]     = m0;
            s_pool[((pr0+1)*16 + pxl)*65 + co] = m1;
        }
    }
    __syncthreads();

    // per-block stats partials
    if (tid < 64) {
        float S = 0.f, Q = 0.f;
#pragma unroll
        for (int i = 0; i < 8; i++) { S += s_sum[tid*8 + i]; Q += s_sq[tid*8 + i]; }
        g_part1[(tid*512 + bid)*2]     = S;
        g_part1[(tid*512 + bid)*2 + 1] = Q;
    }

    // pooled raw write-out, NHWC flat, coalesced
    int base = (((b*128 + (y0 >> 1))*128) + (x0 >> 1))*64;
    for (int i = tid; i < 16384; i += 256) {
        int r = i >> 10, j = i & 1023;
        int px = j >> 6, co = j & 63;
        g_praw[base + r*8192 + j] = s_pool[(r*16 + px)*65 + co];
    }
}

// ============================================================
// finalize BN1: one block per channel, sum 512 partials
// ============================================================
__global__ void __launch_bounds__(256) finalize1_k(const float* __restrict__ gamma,
                                                   const float* __restrict__ beta)
{
    int c = blockIdx.x, t = threadIdx.x;
    float s = 0.f, q = 0.f;
    for (int i = t; i < 512; i += 256) {
        s += g_part1[(c*512 + i)*2];
        q += g_part1[(c*512 + i)*2 + 1];
    }
    __shared__ float ss[256], s2[256];
    ss[t] = s; s2[t] = q; __syncthreads();
    for (int o = 128; o > 0; o >>= 1) {
        if (t < o) { ss[t] += ss[t+o]; s2[t] += s2[t+o]; }
        __syncthreads();
    }
    if (t == 0) {
        float inv = 1.f / (float)BNCNT;
        float mean = ss[0] * inv;
        float var = s2[0] * inv - mean*mean;
        float scale = gamma[c] * rsqrtf(var + EPSBN);
        g_bn1[c*2]   = scale;
        g_bn1[c*2+1] = beta[c] - mean*scale;
    }
}

// ============================================================
// bnsplit: affine+relu on pooled raw -> g_pool fp32 + bf16 hi/lo
// ============================================================
__global__ void __launch_bounds__(256) bnsplit_k()
{
    __shared__ float s_ss[128];
    int t = threadIdx.x;
    if (t < 128) s_ss[t] = g_bn1[t];
    __syncthreads();
    const float4* src = (const float4*)g_praw;
    float4* dst = (float4*)g_pool;
    uint2* dhi = (uint2*)g_fhi;
    uint2* dlo = (uint2*)g_flo;
    int e4 = blockIdx.x*1024 + t;
#pragma unroll
    for (int it = 0; it < 4; it++, e4 += 256) {
        int co0 = (e4 << 2) & 63;
        float4 v = src[e4];
        v.x = fmaxf(fmaf(v.x, s_ss[co0*2],   s_ss[co0*2+1]), 0.f);
        v.y = fmaxf(fmaf(v.y, s_ss[co0*2+2], s_ss[co0*2+3]), 0.f);
        v.z = fmaxf(fmaf(v.z, s_ss[co0*2+4], s_ss[co0*2+5]), 0.f);
        v.w = fmaxf(fmaf(v.w, s_ss[co0*2+6], s_ss[co0*2+7]), 0.f);
        dst[e4] = v;
        __nv_bfloat16 hx = __float2bfloat16(v.x), hy = __float2bfloat16(v.y);
        __nv_bfloat16 hz = __float2bfloat16(v.z), hw = __float2bfloat16(v.w);
        uint2 hh;
        hh.x = ((unsigned)__bfloat16_as_ushort(hy) << 16) | __bfloat16_as_ushort(hx);
        hh.y = ((unsigned)__bfloat16_as_ushort(hw) << 16) | __bfloat16_as_ushort(hz);
        dhi[e4] = hh;
        __nv_bfloat16 lx = __float2bfloat16(v.x - __bfloat162float(hx));
        __nv_bfloat16 ly = __float2bfloat16(v.y - __bfloat162float(hy));
        __nv_bfloat16 lz = __float2bfloat16(v.z - __bfloat162float(hz));
        __nv_bfloat16 lw = __float2bfloat16(v.w - __bfloat162float(hw));
        uint2 ll;
        ll.x = ((unsigned)__bfloat16_as_ushort(ly) << 16) | __bfloat16_as_ushort(lx);
        ll.y = ((unsigned)__bfloat16_as_ushort(lw) << 16) | __bfloat16_as_ushort(lz);
        dlo[e4] = ll;
    }
}

// ============================================================
// embed prep: ||e||^2 + bf16 hi/lo split
// ============================================================
__global__ void __launch_bounds__(256) epre_k(const float* __restrict__ embed)
{
    int t = threadIdx.x;
    int code = blockIdx.x*8 + (t >> 5);
    int lane = t & 31;
    float a = embed[code*64 + lane];
    float bb = embed[code*64 + 32 + lane];
    __nv_bfloat16 ah = __float2bfloat16(a);
    __nv_bfloat16 bh = __float2bfloat16(bb);
    g_ehi[code*64 + lane] = ah;
    g_ehi[code*64 + 32 + lane] = bh;
    g_elo[code*64 + lane] = __float2bfloat16(a - __bfloat162float(ah));
    g_elo[code*64 + 32 + lane] = __float2bfloat16(bb - __bfloat162float(bh));
    float s = a*a + bb*bb;
#pragma unroll
    for (int o = 16; o > 0; o >>= 1)
        s += __shfl_down_sync(0xffffffffu, s, o);
    if (lane == 0) g_e2[code] = s;
}

// ============================================================
// VQ via tensor cores (bf16 hi/lo 3-GEMM) + top-2 + exact refine
// + gather + loss partial + direct index output.
// ============================================================
__global__ void __launch_bounds__(256,2) vq_k(const float* __restrict__ embed,
                                              float* __restrict__ out)
{
    __shared__ __align__(16) __nv_bfloat16 s_ahi[128*64];
    __shared__ __align__(16) __nv_bfloat16 s_alo[128*64];
    __shared__ __align__(16) __nv_bfloat16 s_ehi[64*64];
    __shared__ __align__(16) __nv_bfloat16 s_elo[64*64];
    int t = threadIdx.x;
    int warp = t >> 5, lane = t & 31;
    int row0 = blockIdx.x * 128;

    {
        const uint4* sh = (const uint4*)(g_fhi + row0*64);
        const uint4* sl = (const uint4*)(g_flo + row0*64);
        uint4* dh = (uint4*)s_ahi;
        uint4* dl = (uint4*)s_alo;
#pragma unroll
        for (int j = 0; j < 4; j++) {
            int e = t + j*256;
            int r = e >> 3, kc = e & 7;
            int dst = r*8 + (kc ^ (r & 7));
            dh[dst] = sh[e];
            dl[dst] = sl[e];
        }
    }
    const uint4* eh4 = (const uint4*)g_ehi;
    const uint4* el4 = (const uint4*)g_elo;
    uint4 bufh[2], bufl[2];
#pragma unroll
    for (int j = 0; j < 2; j++) {
        bufh[j] = eh4[t + j*256];
        bufl[j] = el4[t + j*256];
    }
    __syncthreads();

    unsigned int afrag[2][4][4];
    {
        unsigned int aHiB = (unsigned int)__cvta_generic_to_shared(s_ahi);
        unsigned int aLoB = (unsigned int)__cvta_generic_to_shared(s_alo);
        int ar = warp*16 + (lane & 15);
        int ahalf = lane >> 4;
#pragma unroll
        for (int ks = 0; ks < 4; ks++) {
            unsigned int off = (unsigned int)(ar*128 + (((ks*2 + ahalf) ^ (ar & 7)) << 4));
            LDSM_X4(afrag[0][ks][0], afrag[0][ks][1], afrag[0][ks][2], afrag[0][ks][3], aHiB + off);
            LDSM_X4(afrag[1][ks][0], afrag[1][ks][1], afrag[1][ks][2], afrag[1][ks][3], aLoB + off);
        }
    }

    float d1v[2] = {INFINITY, INFINITY}, d2v[2] = {INFINITY, INFINITY};
    int   i1v[2] = {0, 0},               i2v[2] = {0, 0};
    unsigned int eHiB = (unsigned int)__cvta_generic_to_shared(s_ehi);
    unsigned int eLoB = (unsigned int)__cvta_generic_to_shared(s_elo);
    int nb = lane & 7;
    int halfB = (lane >> 3) & 1;

    for (int ch = 0; ch < 16; ch++) {
        __syncthreads();
        {
            uint4* dh = (uint4*)s_ehi;
            uint4* dl = (uint4*)s_elo;
#pragma unroll
            for (int j = 0; j < 2; j++) {
                int e = t + j*256;
                int r = e >> 3, kc = e & 7;
                int dst = r*8 + (kc ^ (r & 7));
                dh[dst] = bufh[j];
                dl[dst] = bufl[j];
            }
        }
        __syncthreads();
        if (ch + 1 < 16) {
#pragma unroll
            for (int j = 0; j < 2; j++) {
                bufh[j] = eh4[(ch+1)*512 + t + j*256];
                bufl[j] = el4[(ch+1)*512 + t + j*256];
            }
        }

        float acc[8][4];
#pragma unroll
        for (int f = 0; f < 8; f++)
#pragma unroll
            for (int q = 0; q < 4; q++) acc[f][q] = 0.f;

#pragma unroll
        for (int ks = 0; ks < 4; ks++) {
            unsigned int pc = (unsigned int)(((ks*2 + halfB) ^ nb) << 4) + (unsigned int)(nb*128);
#pragma unroll
            for (int f = 0; f < 8; f++) {
                unsigned int off = pc + (unsigned int)(f*1024);
                unsigned int bh0, bh1, bl0, bl1;
                LDSM_X2(bh0, bh1, eHiB + off);
                LDSM_X2(bl0, bl1, eLoB + off);
                MMA16816(acc[f], afrag[0][ks][0], afrag[0][ks][1], afrag[0][ks][2], afrag[0][ks][3], bh0, bh1);
                MMA16816(acc[f], afrag[0][ks][0], afrag[0][ks][1], afrag[0][ks][2], afrag[0][ks][3], bl0, bl1);
                MMA16816(acc[f], afrag[1][ks][0], afrag[1][ks][1], afrag[1][ks][2], afrag[1][ks][3], bh0, bh1);
            }
        }

        int cb = ch*64 + (lane & 3)*2;
#pragma unroll
        for (int f = 0; f < 8; f++) {
            int c0 = cb + f*8, c1 = c0 + 1;
            float e20 = g_e2[c0], e21 = g_e2[c1];
            ins2(fmaf(-2.f, acc[f][0], e20), c0, d1v[0], i1v[0], d2v[0], i2v[0]);
            ins2(fmaf(-2.f, acc[f][1], e21), c1, d1v[0], i1v[0], d2v[0], i2v[0]);
            ins2(fmaf(-2.f, acc[f][2], e20), c0, d1v[1], i1v[1], d2v[1], i2v[1]);
            ins2(fmaf(-2.f, acc[f][3], e21), c1, d1v[1], i1v[1], d2v[1], i2v[1]);
        }
    }

    const unsigned FULL = 0xffffffffu;
#pragma unroll
    for (int off = 2; off > 0; off >>= 1) {
#pragma unroll
        for (int s = 0; s < 2; s++) {
            float od1 = __shfl_down_sync(FULL, d1v[s], off, 4);
            int   oi1 = __shfl_down_sync(FULL, i1v[s], off, 4);
            float od2 = __shfl_down_sync(FULL, d2v[s], off, 4);
            int   oi2 = __shfl_down_sync(FULL, i2v[s], off, 4);
            if (better(od1, oi1, d1v[s], i1v[s])) {
                if (better(d1v[s], i1v[s], od2, oi2)) { d2v[s] = d1v[s]; i2v[s] = i1v[s]; }
                else                                  { d2v[s] = od2;    i2v[s] = oi2; }
                d1v[s] = od1; i1v[s] = oi1;
            } else if (better(od1, oi1, d2v[s], i2v[s])) {
                d2v[s] = od1; i2v[s] = oi1;
            }
        }
    }
    __syncthreads();
    int* s_b1 = (int*)s_ehi;
    int* s_b2 = s_b1 + 128;
    if ((lane & 3) == 0) {
        int r = warp*16 + (lane >> 2);
        s_b1[r]     = i1v[0];  s_b2[r]     = i2v[0];
        s_b1[r + 8] = i1v[1];  s_b2[r + 8] = i2v[1];
    }
    __syncthreads();

    // exact fp32 refine between top-2 candidates (vectorized)
    if (t < 128) {
        int ia = s_b1[t], ib = s_b2[t];
        if (ib != ia) {
            const float4* frow = (const float4*)(g_pool + (size_t)(row0 + t)*64);
            const float4* ea = (const float4*)(embed + (size_t)ia*64);
            const float4* eb = (const float4*)(embed + (size_t)ib*64);
            float da = 0.f, db = 0.f;
#pragma unroll
            for (int k = 0; k < 16; k++) {
                float4 f = frow[k], va = ea[k], vb = eb[k];
                da = fmaf(f.x, va.x, da); da = fmaf(f.y, va.y, da);
                da = fmaf(f.z, va.z, da); da = fmaf(f.w, va.w, da);
                db = fmaf(f.x, vb.x, db); db = fmaf(f.y, vb.y, db);
                db = fmaf(f.z, vb.z, db); db = fmaf(f.w, vb.w, db);
            }
            float dda = fmaf(-2.f, da, g_e2[ia]);
            float ddb = fmaf(-2.f, db, g_e2[ib]);
            if (better(ddb, ib, dda, ia)) s_b1[t] = ib;
        }
    }
    __syncthreads();

    float lacc = 0.f;
    for (int e = t; e < 8192; e += 256) {
        int r = e >> 6, d = e & 63;
        int ci = s_b1[r];
        float qv = embed[ci*64 + d];
        float fv = g_pool[(row0 + r)*64 + d];
        float df = qv - fv;
        lacc = fmaf(df, df, lacc);
        g_quant[row0*64 + e] = qv;
    }
    if (t < 128) out[YELEMS + row0 + t] = (float)s_b1[t];

    float* s_red = (float*)s_elo;
    s_red[t] = lacc;
    __syncthreads();
    for (int o = 128; o > 0; o >>= 1) {
        if (t < o) s_red[t] += s_red[t+o];
        __syncthreads();
    }
    if (t == 0) g_losspart[blockIdx.x] = s_red[0];
}

// ============================================================
// collapse conv2 3x3-over-upsample into 4 phase x 2x2 kernels
// ============================================================
__global__ void __launch_bounds__(256) collapse_k(const float* __restrict__ w2)
{
    int e = blockIdx.x*256 + threadIdx.x;
    if (e >= 48*64) return;
    int d = e & 63;
    int rest = e >> 6;
    int tap = rest & 3;
    int tx_ = tap & 1, ty_ = tap >> 1;
    int co = (rest >> 2) % 3;
    int ph = rest / 12;
    int px = ph & 1, py = ph >> 1;
    float s = 0.f;
    for (int ky = 0; ky < 3; ky++) {
        int mapy = (py == 0) ? ((ky == 0) ? 0 : 1) : ((ky < 2) ? 0 : 1);
        if (mapy != ty_) continue;
        for (int kx = 0; kx < 3; kx++) {
            int mapx = (px == 0) ? ((kx == 0) ? 0 : 1) : ((kx < 2) ? 0 : 1);
            if (mapx != tx_) continue;
            s += w2[((co*64 + d)*3 + ky)*3 + kx];
        }
    }
    g_cw[e] = s;
}

// ============================================================
// decoder: nearest-x2 upsample fused with conv2 (collapsed 2x2)
// ============================================================
#define DCK 16
__global__ void __launch_bounds__(256) conv2up_k(const float* __restrict__ bias)
{
    __shared__ float s_q[DCK][18][34];
    __shared__ float s_cw[48][DCK];
    int t = threadIdx.x;
    int tx = t & 15, ty = t >> 4;
    int x0 = blockIdx.x*32, y0 = blockIdx.y*16, bb = blockIdx.z;

    float acc[2][2][2][3];
#pragma unroll
    for (int a1 = 0; a1 < 2; a1++)
#pragma unroll
        for (int a2 = 0; a2 < 2; a2++)
#pragma unroll
            for (int a3 = 0; a3 < 2; a3++)
#pragma unroll
                for (int a4 = 0; a4 < 3; a4++) acc[a1][a2][a3][a4] = 0.f;

    for (int ch = 0; ch < 64/DCK; ch++) {
        __syncthreads();
        for (int e = t; e < 48*DCK; e += 256) {
            int row = e >> 4, dl = e & (DCK-1);
            s_cw[row][dl] = g_cw[row*64 + ch*DCK + dl];
        }
        for (int e = t; e < 612*DCK; e += 256) {
            int dl = e & (DCK-1);
            int cell = e >> 4;
            int r = cell / 34, c = cell % 34;
            int qy = y0 - 1 + r, qx = x0 - 1 + c;
            float v = 0.f;
            if (qy >= 0 && qy < 128 && qx >= 0 && qx < 128)
                v = g_quant[((bb*128 + qy)*128 + qx)*64 + ch*DCK + dl];
            s_q[dl][r][c] = v;
        }
        __syncthreads();

#pragma unroll 4
        for (int dl = 0; dl < DCK; dl++) {
            float qv[3][4];
#pragma unroll
            for (int a = 0; a < 3; a++)
#pragma unroll
                for (int c = 0; c < 4; c++)
                    qv[a][c] = s_q[dl][ty + a][2*tx + c];
#pragma unroll
            for (int co = 0; co < 3; co++)
#pragma unroll
                for (int py = 0; py < 2; py++)
#pragma unroll
                    for (int px = 0; px < 2; px++) {
#pragma unroll
                        for (int ty_ = 0; ty_ < 2; ty_++)
#pragma unroll
                            for (int tx_ = 0; tx_ < 2; tx_++) {
                                float wv = s_cw[((py*2+px)*3+co)*4 + ty_*2+tx_][dl];
#pragma unroll
                                for (int xi = 0; xi < 2; xi++)
                                    acc[xi][py][px][co] =
                                        fmaf(qv[py+ty_][xi+px+tx_], wv, acc[xi][py][px][co]);
                            }
                    }
        }
    }

    int qy = y0 + ty;
#pragma unroll
    for (int co = 0; co < 3; co++) {
        float bv = bias[co];
#pragma unroll
        for (int xi = 0; xi < 2; xi++) {
            int qx = x0 + 2*tx + xi;
#pragma unroll
            for (int py = 0; py < 2; py++)
#pragma unroll
                for (int px = 0; px < 2; px++) {
                    int Y = 2*qy + py, X = 2*qx + px;
                    g_y2[((bb*3 + co) << 16) + (Y << 8) + X] = acc[xi][py][px][co] + bv;
                }
        }
    }
}

// ============================================================
// BN2 stats (float4)
// ============================================================
__global__ void __launch_bounds__(256) stats3_k()
{
    int c = blockIdx.x, s = blockIdx.y, t = threadIdx.x;
    const float4* src = (const float4*)g_y2;
    float sum = 0.f, sq = 0.f;
    int i0 = s * 4096;
    for (int i = i0 + t; i < i0 + 4096; i += 256) {
        int b = i >> 14, p4 = i & 16383;
        float4 v = src[((b*3 + c) << 14) + p4];
        sum += v.x + v.y + v.z + v.w;
        sq = fmaf(v.x, v.x, sq); sq = fmaf(v.y, v.y, sq);
        sq = fmaf(v.z, v.z, sq); sq = fmaf(v.w, v.w, sq);
    }
    __shared__ float ss[256], s2[256];
    ss[t] = sum; s2[t] = sq; __syncthreads();
    for (int o = 128; o > 0; o >>= 1) {
        if (t < o) { ss[t] += ss[t+o]; s2[t] += s2[t+o]; }
        __syncthreads();
    }
    if (t == 0) { g_part2[(c*32 + s)*2] = ss[0]; g_part2[(c*32 + s)*2 + 1] = s2[0]; }
}

// finalize BN2 + loss output
__global__ void __launch_bounds__(256) fin2loss_k(const float* __restrict__ gamma,
                                                  const float* __restrict__ beta,
                                                  float* __restrict__ out)
{
    int t = threadIdx.x;
    if (t < 3) {
        float sum = 0.f, sq = 0.f;
        for (int s = 0; s < 32; s++) { sum += g_part2[(t*32+s)*2]; sq += g_part2[(t*32+s)*2+1]; }
        float inv = 1.f / (float)BNCNT;
        float mean = sum * inv;
        float var = sq * inv - mean*mean;
        float scale = gamma[t] * rsqrtf(var + EPSBN);
        g_bn2[t*2]   = scale;
        g_bn2[t*2+1] = beta[t] - mean*scale;
    }
    __shared__ float s[256];
    s[t] = g_losspart[t] + g_losspart[t+256] + g_losspart[t+512] + g_losspart[t+768];
    __syncthreads();
    for (int o = 128; o > 0; o >>= 1) {
        if (t < o) s[t] += s[t+o];
        __syncthreads();
    }
    if (t == 0) out[YELEMS + NPTS] = 0.25f * s[0] / (float)(NPTS * DD);
}

// ============================================================
// BN2 apply + tanh -> d_out (float4)
// ============================================================
__global__ void __launch_bounds__(256) bn2tanh_k(float* __restrict__ out)
{
    int e4 = blockIdx.x*256 + threadIdx.x;
    int c = (e4 >> 14) % 3;
    float sc = g_bn2[c*2], sh = g_bn2[c*2+1];
    float4 v = ((const float4*)g_y2)[e4];
    float4 r;
    r.x = tanhf(fmaf(v.x, sc, sh));
    r.y = tanhf(fmaf(v.y, sc, sh));
    r.z = tanhf(fmaf(v.z, sc, sh));
    r.w = tanhf(fmaf(v.w, sc, sh));
    ((float4*)out)[e4] = r;
}

// ============================================================
extern "C" void kernel_launch(void* const* d_in, const int* in_sizes, int n_in,
                              void* d_out, int out_size)
{
    const float* x   = (const float*)d_in[0];
    const float* w1  = (const float*)d_in[1];
    const float* b1  = (const float*)d_in[2];
    const float* g1  = (const float*)d_in[3];
    const float* be1 = (const float*)d_in[4];
    const float* em  = (const float*)d_in[5];
    const float* w2  = (const float*)d_in[6];
    const float* b2  = (const float*)d_in[7];
    const float* g2  = (const float*)d_in[8];
    const float* be2 = (const float*)d_in[9];
    float* out = (float*)d_out;
    (void)in_sizes; (void)n_in; (void)out_size;

    const int POOL_SMEM = 16*16*65*4;   // 66560
    cudaFuncSetAttribute(conv1pool_k, cudaFuncAttributeMaxDynamicSharedMemorySize, POOL_SMEM);

    epre_k<<<128, 256>>>(em);                                       // 0
    conv1pool_k<<<dim3(8,8,8), dim3(32,8), POOL_SMEM>>>(x, w1, b1); // 1
    finalize1_k<<<64, 256>>>(g1, be1);                              // 2
    bnsplit_k<<<NPTS*DD/4096, 256>>>();                             // 3
    collapse_k<<<12, 256>>>(w2);                                    // 4
    vq_k<<<NPTS/128, 256>>>(em, out);                               // 5
    conv2up_k<<<dim3(4,8,8), 256>>>(b2);                            // 6
    stats3_k<<<dim3(3,32), 256>>>();                                // 7
    fin2loss_k<<<1, 256>>>(g2, be2, out);                           // 8
    bn2tanh_k<<<YELEMS/1024, 256>>>(out);                           // 9
}